// round 5
// baseline (speedup 1.0000x reference)
#include <cuda_runtime.h>
#include <cuda_bf16.h>
#include <cstdint>

#define VOCAB 30000
#define TT    512
#define BATCH 4096
#define HH    100
#define EE    32
#define BB    32       // batch per CTA
#define NBLK  128      // BATCH / BB
#define NTH   416      // 13 warps; 400 active compute threads
#define ACT   400
#define HTP   68       // padded htd row: 32 b * 2 (dup) + 4 pad floats
#define HTSZ  (HH * HTP)   // 6800 floats per buffer

// 48 MB table: xpre[v][j][gate] = bias_g[j] + emb[v]·Wg[0:32, j]; gate order f,i,o,g
__device__ float g_xpre[(size_t)VOCAB * HH * 4];

typedef unsigned long long u64;

__device__ __forceinline__ float fsigm(float z) {
    return __fdividef(1.f, 1.f + __expf(-z));
}
__device__ __forceinline__ float ftanh(float z) {
    return 1.f - __fdividef(2.f, __expf(2.f * z) + 1.f);
}
__device__ __forceinline__ void ffma2(u64& d, u64 a, u64 b) {
    asm("fma.rn.f32x2 %0, %1, %2, %0;" : "+l"(d) : "l"(a), "l"(b));
}
__device__ __forceinline__ u64 fadd2(u64 a, u64 b) {
    u64 r; asm("add.rn.f32x2 %0, %1, %2;" : "=l"(r) : "l"(a), "l"(b)); return r;
}
__device__ __forceinline__ u64 mk2(float lo, float hi) {
    u64 r; asm("mov.b64 %0, {%1, %2};" : "=l"(r) : "f"(lo), "f"(hi)); return r;
}
__device__ __forceinline__ float2 unpack2(u64 v) {
    float2 f; asm("mov.b64 {%0, %1}, %2;" : "=f"(f.x), "=f"(f.y) : "l"(v)); return f;
}

// ---------------------------------------------------------------------------
// Kernel 1: xpre[v][j][4] = bias + emb[v](1x32) · W[0:32]  (gate-interleaved)
// ---------------------------------------------------------------------------
__global__ void xpre_kernel(const float* __restrict__ emb,
                            const float* __restrict__ Wf, const float* __restrict__ bf,
                            const float* __restrict__ Wi, const float* __restrict__ bi,
                            const float* __restrict__ Wo, const float* __restrict__ bo,
                            const float* __restrict__ Wc, const float* __restrict__ bc) {
    int v = blockIdx.x;
    __shared__ float e[EE];
    if (threadIdx.x < EE) e[threadIdx.x] = emb[v * EE + threadIdx.x];
    __syncthreads();
    for (int n = threadIdx.x; n < HH * 4; n += blockDim.x) {
        int j = n >> 2, gate = n & 3;
        const float* W = (gate == 0) ? Wf : (gate == 1) ? Wi : (gate == 2) ? Wo : Wc;
        const float* b = (gate == 0) ? bf : (gate == 1) ? bi : (gate == 2) ? bo : bc;
        float s = b[j];
#pragma unroll
        for (int k = 0; k < EE; k++) s = fmaf(e[k], W[k * HH + j], s);
        g_xpre[((size_t)v * HH + j) * 4 + gate] = s;
    }
}

// ---------------------------------------------------------------------------
// Kernel 2: persistent fused LSTM. One CTA = 32 batch elems, 511 steps.
// SMEM: W[k][j][4] (160KB), htd[2][k][b*2] duplicated h (54.4KB), tokens.
// Thread (bg=tid/100, j=tid%100) owns output j (all 4 gates) for 8 batches.
// ---------------------------------------------------------------------------
__global__ void __launch_bounds__(NTH, 1)
lstm_kernel(const int* __restrict__ data32,
            const float* __restrict__ Wf, const float* __restrict__ Wi,
            const float* __restrict__ Wo4, const float* __restrict__ Wc,
            const float* __restrict__ WoOut, const float* __restrict__ boOut,
            float* __restrict__ out) {
    extern __shared__ float smem[];
    float* Ws  = smem;                       // [100k][100j][4g]
    float* htd = smem + 40000;               // [2][100k][68] (b*2 duplicated)
    int*   itk = (int*)(smem + 40000 + 2 * HTSZ);
    int*   toks = itk;                       // [2][32]
    int*   ltok = itk + 2 * BB;              // [32]
    int*   flag = itk + 3 * BB;              // [1]

    const int tid = threadIdx.x;
    const int b0  = blockIdx.x * BB;

    if (tid == 0) {
        int is64 = 1;
        for (int i = 0; i < 64; i++)
            if (data32[2 * i + 1] != 0) { is64 = 0; break; }
        flag[0] = is64;
    }
    // stage W rows 32..131: Ws[(k*100+j)*4+g] = Wg[(32+k)*100 + j]
    for (int idx = tid; idx < HH * HH * 4; idx += NTH) {
        int g = idx & 3, kj = idx >> 2, k = kj / HH, j = kj % HH;
        const float* W = (g == 0) ? Wf : (g == 1) ? Wi : (g == 2) ? Wo4 : Wc;
        Ws[idx] = W[(EE + k) * HH + j];
    }
    for (int idx = tid; idx < HTSZ; idx += NTH) htd[idx] = 0.f;   // buffer 0 only
    __syncthreads();

    const int is64 = flag[0];
    if (tid < BB) {
        long long base = (long long)(b0 + tid) * TT;
        ltok[tid] = is64 ? data32[2 * (base + TT - 1)] : data32[base + TT - 1];
        toks[tid] = is64 ? data32[2 * base]            : data32[base];
    }
    __syncthreads();

    const bool active = (tid < ACT);
    const int  bg = tid / 100;   // 0..3, owns batches bg*8..bg*8+7
    const int  j  = tid % 100;   // output index (all 4 gates)

    float c[8], hreg[8];
#pragma unroll
    for (int i = 0; i < 8; i++) { c[i] = 0.f; hreg[i] = 0.f; }

    int cur = 0;
    for (int t = 0; t < TT - 1; ++t) {
        if (tid < BB) {
            long long base = (long long)(b0 + tid) * TT + (t + 1);
            toks[(cur ^ 1) * BB + tid] = is64 ? data32[2 * base] : data32[base];
        }

        if (active) {
            // gather x-part preacts early (consumed in epilogue)
            int tk[8];
            u64 xfi[8], xog[8];
#pragma unroll
            for (int i = 0; i < 8; i++) {
                tk[i] = toks[cur * BB + bg * 8 + i];
                float4 xp = __ldg((const float4*)(g_xpre + ((size_t)tk[i] * HH + j) * 4));
                xfi[i] = mk2(xp.x, xp.y);
                xog[i] = mk2(xp.z, xp.w);
            }
            u64 afi[8], aog[8];
#pragma unroll
            for (int i = 0; i < 8; i++) { afi[i] = 0ull; aog[i] = 0ull; }

            const float* Wb = Ws + j * 4;                 // +k*400
            const float* Hb = htd + cur * HTSZ + bg * 16; // +k*HTP
#pragma unroll 2
            for (int k = 0; k < HH; k += 2) {
                float4 w0 = *(const float4*)(Wb + (size_t)k * 400);
                float4 w1 = *(const float4*)(Wb + (size_t)k * 400 + 400);
                ulonglong2 h00 = *(const ulonglong2*)(Hb + k * HTP);
                ulonglong2 h01 = *(const ulonglong2*)(Hb + k * HTP + 4);
                ulonglong2 h02 = *(const ulonglong2*)(Hb + k * HTP + 8);
                ulonglong2 h03 = *(const ulonglong2*)(Hb + k * HTP + 12);
                ulonglong2 h10 = *(const ulonglong2*)(Hb + k * HTP + HTP);
                ulonglong2 h11 = *(const ulonglong2*)(Hb + k * HTP + HTP + 4);
                ulonglong2 h12 = *(const ulonglong2*)(Hb + k * HTP + HTP + 8);
                ulonglong2 h13 = *(const ulonglong2*)(Hb + k * HTP + HTP + 12);
                u64 wfi0 = mk2(w0.x, w0.y), wog0 = mk2(w0.z, w0.w);
                u64 wfi1 = mk2(w1.x, w1.y), wog1 = mk2(w1.z, w1.w);
                ffma2(afi[0], h00.x, wfi0); ffma2(aog[0], h00.x, wog0);
                ffma2(afi[1], h00.y, wfi0); ffma2(aog[1], h00.y, wog0);
                ffma2(afi[2], h01.x, wfi0); ffma2(aog[2], h01.x, wog0);
                ffma2(afi[3], h01.y, wfi0); ffma2(aog[3], h01.y, wog0);
                ffma2(afi[4], h02.x, wfi0); ffma2(aog[4], h02.x, wog0);
                ffma2(afi[5], h02.y, wfi0); ffma2(aog[5], h02.y, wog0);
                ffma2(afi[6], h03.x, wfi0); ffma2(aog[6], h03.x, wog0);
                ffma2(afi[7], h03.y, wfi0); ffma2(aog[7], h03.y, wog0);
                ffma2(afi[0], h10.x, wfi1); ffma2(aog[0], h10.x, wog1);
                ffma2(afi[1], h10.y, wfi1); ffma2(aog[1], h10.y, wog1);
                ffma2(afi[2], h11.x, wfi1); ffma2(aog[2], h11.x, wog1);
                ffma2(afi[3], h11.y, wfi1); ffma2(aog[3], h11.y, wog1);
                ffma2(afi[4], h12.x, wfi1); ffma2(aog[4], h12.x, wog1);
                ffma2(afi[5], h12.y, wfi1); ffma2(aog[5], h12.y, wog1);
                ffma2(afi[6], h13.x, wfi1); ffma2(aog[6], h13.x, wog1);
                ffma2(afi[7], h13.y, wfi1); ffma2(aog[7], h13.y, wog1);
            }

            // epilogue: activate, masked c/h update, write duplicated h
            float* Hn = htd + (cur ^ 1) * HTSZ + j * HTP + bg * 16;
#pragma unroll
            for (int i = 0; i < 8; i++) {
                float2 zfi = unpack2(fadd2(afi[i], xfi[i]));
                float2 zog = unpack2(fadd2(aog[i], xog[i]));
                float f  = fsigm(zfi.x);
                float ii = fsigm(zfi.y);
                float o  = fsigm(zog.x);
                float g  = ftanh(zog.y);
                float cn = fmaf(c[i], f, ii * g);
                bool  m  = (tk[i] != ltok[bg * 8 + i]);
                float cv = m ? cn : c[i];
                float hv = m ? o * ftanh(cn) : hreg[i];
                c[i] = cv; hreg[i] = hv;
                *(u64*)(Hn + i * 2) = mk2(hv, hv);
            }
        }
        cur ^= 1;
        __syncthreads();
    }

    // output head: out[b] = sigmoid(h·Wo + bo); final h in htd[cur]
    if (tid < BB) {
        const float* Hf = htd + cur * HTSZ + tid * 2;
        float z = boOut[0];
#pragma unroll 4
        for (int k = 0; k < HH; k++) z = fmaf(Hf[k * HTP], WoOut[k], z);
        out[b0 + tid] = fsigm(z);
    }
}

// ---------------------------------------------------------------------------
extern "C" void kernel_launch(void* const* d_in, const int* in_sizes, int n_in,
                              void* d_out, int out_size) {
    const int*   data = (const int*)  d_in[0];   // int64 or int32 tokens (auto-detected)
    const float* emb  = (const float*)d_in[1];
    const float* Wfh  = (const float*)d_in[2];
    const float* bfh  = (const float*)d_in[3];
    const float* Wih  = (const float*)d_in[4];
    const float* bih  = (const float*)d_in[5];
    const float* Woh  = (const float*)d_in[6];
    const float* boh  = (const float*)d_in[7];
    const float* Wch  = (const float*)d_in[8];
    const float* bch  = (const float*)d_in[9];
    const float* Wo   = (const float*)d_in[10];
    const float* bo   = (const float*)d_in[11];
    float* out = (float*)d_out;

    xpre_kernel<<<VOCAB, 128>>>(emb, Wfh, bfh, Wih, bih, Woh, boh, Wch, bch);

    const size_t smem_bytes = (size_t)(40000 + 2 * HTSZ + 128) * 4;
    cudaFuncSetAttribute(lstm_kernel, cudaFuncAttributeMaxDynamicSharedMemorySize,
                         (int)smem_bytes);
    lstm_kernel<<<NBLK, NTH, smem_bytes>>>(data, Wfh, Wih, Woh, Wch, Wo, bo, out);
}